// round 3
// baseline (speedup 1.0000x reference)
#include <cuda_runtime.h>
#include <cuda_bf16.h>

#define NBINS 4096
#define FULLMASK 0xFFFFFFFFu

// ---------------- device-global state (no allocations allowed) ----------------
__device__ unsigned int g_hist1[NBINS];
__device__ unsigned int g_hist2[NBINS];
__device__ double       g_sum2[NBINS];
__device__ double       g_sum_below;
__device__ unsigned int g_B1;
__device__ long long    g_cbelow1;

// ---------------- K0: zero state ----------------
__global__ void k_zero() {
    int i = blockIdx.x * blockDim.x + threadIdx.x;
    if (i < NBINS) {
        g_hist1[i] = 0u;
        g_hist2[i] = 0u;
        g_sum2[i]  = 0.0;
    }
    if (i == 0) {
        g_sum_below = 0.0;
        g_B1 = 0u;
        g_cbelow1 = 0;
    }
}

__device__ __forceinline__ float rel_err(float o, float t) {
    float r = (t - o) / t;
    return r * r;
}

__device__ __forceinline__ long long keep_k(int n) {
    return (long long)((double)n * 0.97);  // matches python int(N * 0.97)
}

// ---------------- K1: level-1 histogram over err bit-pattern top 12 bits ----------------
__global__ __launch_bounds__(512) void k_hist1(const float* __restrict__ out,
                                               const float* __restrict__ tgt,
                                               int n) {
    __shared__ unsigned int sh[NBINS];
    for (int i = threadIdx.x; i < NBINS; i += blockDim.x) sh[i] = 0u;
    __syncthreads();

    int n4 = n >> 2;
    const float4* __restrict__ o4 = (const float4*)out;
    const float4* __restrict__ t4 = (const float4*)tgt;
    int stride = gridDim.x * blockDim.x;
    for (int i = blockIdx.x * blockDim.x + threadIdx.x; i < n4; i += stride) {
        float4 o = o4[i];
        float4 t = t4[i];
        float e0 = rel_err(o.x, t.x);
        float e1 = rel_err(o.y, t.y);
        float e2 = rel_err(o.z, t.z);
        float e3 = rel_err(o.w, t.w);
        atomicAdd(&sh[__float_as_uint(e0) >> 20], 1u);
        atomicAdd(&sh[__float_as_uint(e1) >> 20], 1u);
        atomicAdd(&sh[__float_as_uint(e2) >> 20], 1u);
        atomicAdd(&sh[__float_as_uint(e3) >> 20], 1u);
    }
    // tail (n not multiple of 4)
    int tail_base = n4 << 2;
    int gtid = blockIdx.x * blockDim.x + threadIdx.x;
    if (tail_base + gtid < n) {
        float e = rel_err(out[tail_base + gtid], tgt[tail_base + gtid]);
        atomicAdd(&sh[__float_as_uint(e) >> 20], 1u);
    }
    __syncthreads();
    for (int i = threadIdx.x; i < NBINS; i += blockDim.x) {
        unsigned int c = sh[i];
        if (c) atomicAdd(&g_hist1[i], c);
    }
}

// ---------------- K2: select level-1 bin (serial scan of 4096 bins; negligible) ----------------
__global__ void k_select1(int n) {
    if (threadIdx.x == 0 && blockIdx.x == 0) {
        long long want = keep_k(n);
        unsigned long long cum = 0;
        for (int i = 0; i < NBINS; i++) {
            unsigned long long c = g_hist1[i];
            if ((long long)cum < want && (long long)(cum + c) >= want) {
                g_B1 = (unsigned int)i;
                g_cbelow1 = (long long)cum;
            }
            cum += c;
        }
    }
}

// ---------------- K3: sum-below + level-2 histogram over bits [19:8] ----------------
__global__ __launch_bounds__(512) void k_pass2(const float* __restrict__ out,
                                               const float* __restrict__ tgt,
                                               int n) {
    __shared__ unsigned int cnt2[NBINS];
    __shared__ float fs2[NBINS];
    __shared__ double wsum[16];
    for (int i = threadIdx.x; i < NBINS; i += blockDim.x) { cnt2[i] = 0u; fs2[i] = 0.0f; }
    __syncthreads();

    unsigned int B1 = g_B1;
    double acc = 0.0;

    int n4 = n >> 2;
    const float4* __restrict__ o4 = (const float4*)out;
    const float4* __restrict__ t4 = (const float4*)tgt;
    int stride = gridDim.x * blockDim.x;
    for (int i = blockIdx.x * blockDim.x + threadIdx.x; i < n4; i += stride) {
        float4 o = o4[i];
        float4 t = t4[i];
        float e[4];
        e[0] = rel_err(o.x, t.x);
        e[1] = rel_err(o.y, t.y);
        e[2] = rel_err(o.z, t.z);
        e[3] = rel_err(o.w, t.w);
#pragma unroll
        for (int j = 0; j < 4; j++) {
            unsigned int key = __float_as_uint(e[j]);
            unsigned int b = key >> 20;
            if (b < B1) {
                acc += (double)e[j];
            } else if (b == B1) {
                unsigned int b2 = (key >> 8) & 0xFFFu;
                atomicAdd(&cnt2[b2], 1u);
                atomicAdd(&fs2[b2], e[j]);
            }
        }
    }
    // tail
    int tail_base = n4 << 2;
    int gtid = blockIdx.x * blockDim.x + threadIdx.x;
    if (tail_base + gtid < n) {
        float e = rel_err(out[tail_base + gtid], tgt[tail_base + gtid]);
        unsigned int key = __float_as_uint(e);
        unsigned int b = key >> 20;
        if (b < B1) acc += (double)e;
        else if (b == B1) {
            unsigned int b2 = (key >> 8) & 0xFFFu;
            atomicAdd(&cnt2[b2], 1u);
            atomicAdd(&fs2[b2], e);
        }
    }

    // reduce per-thread acc across block -> one global double atomic per block
    int lane = threadIdx.x & 31;
    int wid = threadIdx.x >> 5;
#pragma unroll
    for (int off = 16; off >= 1; off >>= 1)
        acc += __shfl_down_sync(FULLMASK, acc, off);
    if (lane == 0) wsum[wid] = acc;
    __syncthreads();
    if (threadIdx.x == 0) {
        double s = 0.0;
        int nw = blockDim.x >> 5;
        for (int w = 0; w < nw; w++) s += wsum[w];
        atomicAdd(&g_sum_below, s);
    }

    // flush level-2 histogram (counts + value partial sums)
    for (int i = threadIdx.x; i < NBINS; i += blockDim.x) {
        unsigned int c = cnt2[i];
        if (c) {
            atomicAdd(&g_hist2[i], c);
            atomicAdd(&g_sum2[i], (double)fs2[i]);
        }
    }
}

// ---------------- K4: finalize ----------------
__global__ __launch_bounds__(512) void k_final(int n, float* __restrict__ result) {
    __shared__ unsigned int sB2;
    __shared__ long long sC2;
    __shared__ double wsum[16];

    long long k = keep_k(n);
    long long m = k - g_cbelow1;  // elements still needed from level-1 bin B1 (>= 1)

    if (threadIdx.x == 0) {
        unsigned long long cum = 0;
        unsigned int bin = 0;
        unsigned long long below = 0;
        for (int i = 0; i < NBINS; i++) {
            unsigned long long c = g_hist2[i];
            if ((long long)cum < m && (long long)(cum + c) >= m) { bin = (unsigned int)i; below = cum; }
            cum += c;
        }
        sB2 = bin;
        sC2 = (long long)below;
    }
    __syncthreads();

    unsigned int B2 = sB2;
    long long cbelow2 = sC2;

    // parallel sum of g_sum2 for bins < B2
    double part = 0.0;
    for (int i = threadIdx.x; i < (int)B2; i += blockDim.x) part += g_sum2[i];
    int lane = threadIdx.x & 31;
    int wid = threadIdx.x >> 5;
#pragma unroll
    for (int off = 16; off >= 1; off >>= 1)
        part += __shfl_down_sync(FULLMASK, part, off);
    if (lane == 0) wsum[wid] = part;
    __syncthreads();
    if (threadIdx.x == 0) {
        double prefix2 = 0.0;
        int nw = blockDim.x >> 5;
        for (int w = 0; w < nw; w++) prefix2 += wsum[w];
        long long r = m - cbelow2;  // elements taken from the boundary level-2 bin
        // boundary value: 12 level-1 bits + 12 level-2 bits known, midpoint of low 8 bits
        unsigned int key = (g_B1 << 20) | (B2 << 8) | 0x80u;
        double v = (double)__uint_as_float(key);
        double total = g_sum_below + prefix2 + (double)r * v;
        result[0] = (float)(total / (double)k);
    }
}

// ---------------- launch ----------------
extern "C" void kernel_launch(void* const* d_in, const int* in_sizes, int n_in,
                              void* d_out, int out_size) {
    const float* output = (const float*)d_in[0];
    const float* target = (const float*)d_in[1];
    int n = in_sizes[0];
    if (n <= 0) return;

    k_zero<<<16, 256>>>();
    k_hist1<<<592, 512>>>(output, target, n);
    k_select1<<<1, 32>>>(n);
    k_pass2<<<592, 512>>>(output, target, n);
    k_final<<<1, 512>>>(n, (float*)d_out);
}

// round 4
// speedup vs baseline: 8.0559x; 8.0559x over previous
#include <cuda_runtime.h>
#include <cuda_bf16.h>

#define NBINS 4096
#define FULLMASK 0xFFFFFFFFu

// ---------------- device-global state (no allocations allowed) ----------------
__device__ unsigned int g_hist1[NBINS];
__device__ unsigned int g_hist2[NBINS];
__device__ double       g_sum2[NBINS];
__device__ double       g_sum_below;
__device__ unsigned int g_B1;
__device__ long long    g_cbelow1;

// ---------------- K0: zero state ----------------
__global__ void k_zero() {
    int i = blockIdx.x * blockDim.x + threadIdx.x;
    if (i < NBINS) {
        g_hist1[i] = 0u;
        g_hist2[i] = 0u;
        g_sum2[i]  = 0.0;
    }
    if (i == 0) {
        g_sum_below = 0.0;
        g_B1 = 0u;
        g_cbelow1 = 0;
    }
}

__device__ __forceinline__ float rel_err(float o, float t) {
    float r = (t - o) / t;
    return r * r;
}

__device__ __forceinline__ long long keep_k(int n) {
    return (long long)((double)n * 0.97);  // matches python int(N * 0.97)
}

// ---------------- parallel bin select: 1024 threads, 4 bins/thread ----------------
// Finds the unique bin where exclusive_cum < want <= inclusive_cum.
// The single matching thread calls the writer lambda-equivalent via out pointers.
__device__ __forceinline__ void select_bin_1024(const unsigned int* __restrict__ hist,
                                                long long want,
                                                unsigned int* out_bin,
                                                unsigned long long* out_below) {
    __shared__ unsigned long long s_warp[32];
    int t = threadIdx.x;          // 0..1023
    int lane = t & 31;
    int wid = t >> 5;

    // each thread loads its 4 contiguous bins with one 16B load
    uint4 v = ((const uint4*)hist)[t];
    unsigned int raw[4] = {v.x, v.y, v.z, v.w};
    unsigned long long thread_tot =
        (unsigned long long)raw[0] + raw[1] + raw[2] + raw[3];

    // warp inclusive scan of thread totals
    unsigned long long s = thread_tot;
#pragma unroll
    for (int off = 1; off < 32; off <<= 1) {
        unsigned long long u = __shfl_up_sync(FULLMASK, s, off);
        if (lane >= off) s += u;
    }
    if (lane == 31) s_warp[wid] = s;
    __syncthreads();
    if (wid == 0) {
        unsigned long long w = s_warp[lane];
        unsigned long long ws = w;
#pragma unroll
        for (int off = 1; off < 32; off <<= 1) {
            unsigned long long u = __shfl_up_sync(FULLMASK, ws, off);
            if (lane >= off) ws += u;
        }
        s_warp[lane] = ws - w;    // exclusive prefix of warp sums
    }
    __syncthreads();

    unsigned long long base = s_warp[wid] + (s - thread_tot);  // exclusive prefix for this thread

    unsigned long long run = base;
#pragma unroll
    for (int j = 0; j < 4; j++) {
        unsigned long long exc = run;
        run += raw[j];
        if ((long long)exc < want && (long long)run >= want) {
            *out_bin = (unsigned int)(t * 4 + j);
            *out_below = exc;
        }
    }
}

// ---------------- K2: select level-1 bin (parallel) ----------------
__global__ __launch_bounds__(1024) void k_select1(int n) {
    long long want = keep_k(n);
    unsigned int bin;
    unsigned long long below;
    __shared__ unsigned int sbin;
    __shared__ unsigned long long sbelow;
    // exactly one thread matches and writes shared; then thread 0 publishes
    select_bin_1024(g_hist1, want, &sbin, &sbelow);
    __syncthreads();
    if (threadIdx.x == 0) {
        g_B1 = sbin;
        g_cbelow1 = (long long)sbelow;
    }
    (void)bin; (void)below;
}

// ---------------- K1: level-1 histogram over err bit-pattern top 12 bits ----------------
__global__ __launch_bounds__(512) void k_hist1(const float* __restrict__ out,
                                               const float* __restrict__ tgt,
                                               int n) {
    __shared__ unsigned int sh[NBINS];
    for (int i = threadIdx.x; i < NBINS; i += blockDim.x) sh[i] = 0u;
    __syncthreads();

    int n4 = n >> 2;
    const float4* __restrict__ o4 = (const float4*)out;
    const float4* __restrict__ t4 = (const float4*)tgt;
    int stride = gridDim.x * blockDim.x;
    for (int i = blockIdx.x * blockDim.x + threadIdx.x; i < n4; i += stride) {
        float4 o = o4[i];
        float4 t = t4[i];
        float e0 = rel_err(o.x, t.x);
        float e1 = rel_err(o.y, t.y);
        float e2 = rel_err(o.z, t.z);
        float e3 = rel_err(o.w, t.w);
        atomicAdd(&sh[__float_as_uint(e0) >> 20], 1u);
        atomicAdd(&sh[__float_as_uint(e1) >> 20], 1u);
        atomicAdd(&sh[__float_as_uint(e2) >> 20], 1u);
        atomicAdd(&sh[__float_as_uint(e3) >> 20], 1u);
    }
    // tail (n not multiple of 4)
    int tail_base = n4 << 2;
    int gtid = blockIdx.x * blockDim.x + threadIdx.x;
    if (tail_base + gtid < n) {
        float e = rel_err(out[tail_base + gtid], tgt[tail_base + gtid]);
        atomicAdd(&sh[__float_as_uint(e) >> 20], 1u);
    }
    __syncthreads();
    for (int i = threadIdx.x; i < NBINS; i += blockDim.x) {
        unsigned int c = sh[i];
        if (c) atomicAdd(&g_hist1[i], c);
    }
}

// ---------------- K3: sum-below + level-2 histogram over bits [19:8] ----------------
__global__ __launch_bounds__(512) void k_pass2(const float* __restrict__ out,
                                               const float* __restrict__ tgt,
                                               int n) {
    __shared__ unsigned int cnt2[NBINS];
    __shared__ float fs2[NBINS];
    __shared__ double wsum[16];
    for (int i = threadIdx.x; i < NBINS; i += blockDim.x) { cnt2[i] = 0u; fs2[i] = 0.0f; }
    __syncthreads();

    unsigned int B1 = g_B1;
    double acc = 0.0;

    int n4 = n >> 2;
    const float4* __restrict__ o4 = (const float4*)out;
    const float4* __restrict__ t4 = (const float4*)tgt;
    int stride = gridDim.x * blockDim.x;
    for (int i = blockIdx.x * blockDim.x + threadIdx.x; i < n4; i += stride) {
        float4 o = o4[i];
        float4 t = t4[i];
        float e[4];
        e[0] = rel_err(o.x, t.x);
        e[1] = rel_err(o.y, t.y);
        e[2] = rel_err(o.z, t.z);
        e[3] = rel_err(o.w, t.w);
#pragma unroll
        for (int j = 0; j < 4; j++) {
            unsigned int key = __float_as_uint(e[j]);
            unsigned int b = key >> 20;
            if (b < B1) {
                acc += (double)e[j];
            } else if (b == B1) {
                unsigned int b2 = (key >> 8) & 0xFFFu;
                atomicAdd(&cnt2[b2], 1u);
                atomicAdd(&fs2[b2], e[j]);
            }
        }
    }
    // tail
    int tail_base = n4 << 2;
    int gtid = blockIdx.x * blockDim.x + threadIdx.x;
    if (tail_base + gtid < n) {
        float e = rel_err(out[tail_base + gtid], tgt[tail_base + gtid]);
        unsigned int key = __float_as_uint(e);
        unsigned int b = key >> 20;
        if (b < B1) acc += (double)e;
        else if (b == B1) {
            unsigned int b2 = (key >> 8) & 0xFFFu;
            atomicAdd(&cnt2[b2], 1u);
            atomicAdd(&fs2[b2], e);
        }
    }

    // reduce per-thread acc across block -> one global double atomic per block
    int lane = threadIdx.x & 31;
    int wid = threadIdx.x >> 5;
#pragma unroll
    for (int off = 16; off >= 1; off >>= 1)
        acc += __shfl_down_sync(FULLMASK, acc, off);
    if (lane == 0) wsum[wid] = acc;
    __syncthreads();
    if (threadIdx.x == 0) {
        double s = 0.0;
        int nw = blockDim.x >> 5;
        for (int w = 0; w < nw; w++) s += wsum[w];
        atomicAdd(&g_sum_below, s);
    }

    // flush level-2 histogram (counts + value partial sums)
    for (int i = threadIdx.x; i < NBINS; i += blockDim.x) {
        unsigned int c = cnt2[i];
        if (c) {
            atomicAdd(&g_hist2[i], c);
            atomicAdd(&g_sum2[i], (double)fs2[i]);
        }
    }
}

// ---------------- K4: finalize (parallel scan + parallel prefix sum) ----------------
__global__ __launch_bounds__(1024) void k_final(int n, float* __restrict__ result) {
    __shared__ unsigned int sB2;
    __shared__ unsigned long long sC2;
    __shared__ double wsum[32];

    long long k = keep_k(n);
    long long m = k - g_cbelow1;  // elements still needed from level-1 bin B1 (>= 1)

    select_bin_1024(g_hist2, m, &sB2, &sC2);
    __syncthreads();

    unsigned int B2 = sB2;
    long long cbelow2 = (long long)sC2;

    // parallel sum of g_sum2 for bins < B2
    double part = 0.0;
    for (int i = threadIdx.x; i < (int)B2; i += blockDim.x) part += g_sum2[i];
    int lane = threadIdx.x & 31;
    int wid = threadIdx.x >> 5;
#pragma unroll
    for (int off = 16; off >= 1; off >>= 1)
        part += __shfl_down_sync(FULLMASK, part, off);
    if (lane == 0) wsum[wid] = part;
    __syncthreads();
    if (threadIdx.x == 0) {
        double prefix2 = 0.0;
        for (int w = 0; w < 32; w++) prefix2 += wsum[w];
        long long r = m - cbelow2;  // elements taken from the boundary level-2 bin
        // boundary value: 12 level-1 bits + 12 level-2 bits known, midpoint of low 8 bits
        unsigned int key = (g_B1 << 20) | (B2 << 8) | 0x80u;
        double v = (double)__uint_as_float(key);
        double total = g_sum_below + prefix2 + (double)r * v;
        result[0] = (float)(total / (double)k);
    }
}

// ---------------- launch ----------------
extern "C" void kernel_launch(void* const* d_in, const int* in_sizes, int n_in,
                              void* d_out, int out_size) {
    const float* output = (const float*)d_in[0];
    const float* target = (const float*)d_in[1];
    int n = in_sizes[0];
    if (n <= 0) return;

    k_zero<<<16, 256>>>();
    k_hist1<<<592, 512>>>(output, target, n);
    k_select1<<<1, 1024>>>(n);
    k_pass2<<<592, 512>>>(output, target, n);
    k_final<<<1, 1024>>>(n, (float*)d_out);
}

// round 7
// speedup vs baseline: 8.0819x; 1.0032x over previous
#include <cuda_runtime.h>
#include <cuda_bf16.h>

#define NBINS 4096
#define FULLMASK 0xFFFFFFFFu

// ---------------- device-global state (no allocations allowed) ----------------
__device__ unsigned int g_hist1[NBINS];
__device__ unsigned int g_hist2[NBINS];
__device__ double       g_sum2[NBINS];
__device__ double       g_sum_below;
__device__ unsigned int g_B1;
__device__ long long    g_cbelow1;

// ---------------- K0: zero state ----------------
__global__ void k_zero() {
    int i = blockIdx.x * blockDim.x + threadIdx.x;
    if (i < NBINS) {
        g_hist1[i] = 0u;
        g_hist2[i] = 0u;
        g_sum2[i]  = 0.0;
    }
    if (i == 0) {
        g_sum_below = 0.0;
        g_B1 = 0u;
        g_cbelow1 = 0;
    }
}

// fast relative error: ~2-3 ulp from __fdividef, far below binning/tolerance needs
__device__ __forceinline__ float rel_err(float o, float t) {
    float r = __fdividef(t - o, t);
    return r * r;
}

__device__ __forceinline__ long long keep_k(int n) {
    return (long long)((double)n * 0.97);  // matches python int(N * 0.97)
}

// ---------------- parallel bin select: 1024 threads, 4 bins/thread ----------------
__device__ __forceinline__ void select_bin_1024(const unsigned int* __restrict__ hist,
                                                long long want,
                                                unsigned int* out_bin,
                                                unsigned long long* out_below) {
    __shared__ unsigned long long s_warp[32];
    int t = threadIdx.x;          // 0..1023
    int lane = t & 31;
    int wid = t >> 5;

    uint4 v = ((const uint4*)hist)[t];
    unsigned int raw[4] = {v.x, v.y, v.z, v.w};
    unsigned long long thread_tot =
        (unsigned long long)raw[0] + raw[1] + raw[2] + raw[3];

    unsigned long long s = thread_tot;
#pragma unroll
    for (int off = 1; off < 32; off <<= 1) {
        unsigned long long u = __shfl_up_sync(FULLMASK, s, off);
        if (lane >= off) s += u;
    }
    if (lane == 31) s_warp[wid] = s;
    __syncthreads();
    if (wid == 0) {
        unsigned long long w = s_warp[lane];
        unsigned long long ws = w;
#pragma unroll
        for (int off = 1; off < 32; off <<= 1) {
            unsigned long long u = __shfl_up_sync(FULLMASK, ws, off);
            if (lane >= off) ws += u;
        }
        s_warp[lane] = ws - w;    // exclusive prefix of warp sums
    }
    __syncthreads();

    unsigned long long base = s_warp[wid] + (s - thread_tot);

    unsigned long long run = base;
#pragma unroll
    for (int j = 0; j < 4; j++) {
        unsigned long long exc = run;
        run += raw[j];
        if ((long long)exc < want && (long long)run >= want) {
            *out_bin = (unsigned int)(t * 4 + j);
            *out_below = exc;
        }
    }
}

// ---------------- K2: select level-1 bin (parallel) ----------------
__global__ __launch_bounds__(1024) void k_select1(int n) {
    long long want = keep_k(n);
    __shared__ unsigned int sbin;
    __shared__ unsigned long long sbelow;
    select_bin_1024(g_hist1, want, &sbin, &sbelow);
    __syncthreads();
    if (threadIdx.x == 0) {
        g_B1 = sbin;
        g_cbelow1 = (long long)sbelow;
    }
}

// ---------------- K1: level-1 histogram over err bit-pattern top 12 bits ----------------
__global__ __launch_bounds__(512) void k_hist1(const float* __restrict__ out,
                                               const float* __restrict__ tgt,
                                               int n) {
    __shared__ unsigned int sh[2 * NBINS];   // dual copies: halve warp conflict degree
    for (int i = threadIdx.x; i < 2 * NBINS; i += blockDim.x) sh[i] = 0u;
    __syncthreads();
    unsigned int* h = &sh[((threadIdx.x >> 5) & 1) * NBINS];

    int n4 = n >> 2;
    const float4* __restrict__ o4 = (const float4*)out;
    const float4* __restrict__ t4 = (const float4*)tgt;
    int stride = gridDim.x * blockDim.x;
    int i = blockIdx.x * blockDim.x + threadIdx.x;

    // unroll-by-2 grid-stride
    for (; i + stride < n4; i += 2 * stride) {
        float4 oa = o4[i];
        float4 ta = t4[i];
        float4 ob = o4[i + stride];
        float4 tb = t4[i + stride];
        atomicAdd(&h[__float_as_uint(rel_err(oa.x, ta.x)) >> 20], 1u);
        atomicAdd(&h[__float_as_uint(rel_err(oa.y, ta.y)) >> 20], 1u);
        atomicAdd(&h[__float_as_uint(rel_err(oa.z, ta.z)) >> 20], 1u);
        atomicAdd(&h[__float_as_uint(rel_err(oa.w, ta.w)) >> 20], 1u);
        atomicAdd(&h[__float_as_uint(rel_err(ob.x, tb.x)) >> 20], 1u);
        atomicAdd(&h[__float_as_uint(rel_err(ob.y, tb.y)) >> 20], 1u);
        atomicAdd(&h[__float_as_uint(rel_err(ob.z, tb.z)) >> 20], 1u);
        atomicAdd(&h[__float_as_uint(rel_err(ob.w, tb.w)) >> 20], 1u);
    }
    for (; i < n4; i += stride) {
        float4 o = o4[i];
        float4 t = t4[i];
        atomicAdd(&h[__float_as_uint(rel_err(o.x, t.x)) >> 20], 1u);
        atomicAdd(&h[__float_as_uint(rel_err(o.y, t.y)) >> 20], 1u);
        atomicAdd(&h[__float_as_uint(rel_err(o.z, t.z)) >> 20], 1u);
        atomicAdd(&h[__float_as_uint(rel_err(o.w, t.w)) >> 20], 1u);
    }
    // tail (n not multiple of 4)
    int tail_base = n4 << 2;
    int gtid = blockIdx.x * blockDim.x + threadIdx.x;
    if (tail_base + gtid < n) {
        float e = rel_err(out[tail_base + gtid], tgt[tail_base + gtid]);
        atomicAdd(&h[__float_as_uint(e) >> 20], 1u);
    }
    __syncthreads();
    for (int b = threadIdx.x; b < NBINS; b += blockDim.x) {
        unsigned int c = sh[b] + sh[NBINS + b];
        if (c) atomicAdd(&g_hist1[b], c);
    }
}

// ---------------- K3: sum-below (float accs) + level-2 histogram over bits [19:8] ----------------
__global__ __launch_bounds__(512) void k_pass2(const float* __restrict__ out,
                                               const float* __restrict__ tgt,
                                               int n) {
    __shared__ unsigned int cnt2[NBINS];
    __shared__ float fs2[NBINS];
    __shared__ double wsum[16];
    for (int i = threadIdx.x; i < NBINS; i += blockDim.x) { cnt2[i] = 0u; fs2[i] = 0.0f; }
    __syncthreads();

    unsigned int B1 = g_B1;
    // four independent float accumulators: short dep chains, negligible rounding
    float a0 = 0.f, a1 = 0.f, a2 = 0.f, a3 = 0.f;

    int n4 = n >> 2;
    const float4* __restrict__ o4 = (const float4*)out;
    const float4* __restrict__ t4 = (const float4*)tgt;
    int stride = gridDim.x * blockDim.x;
    int i = blockIdx.x * blockDim.x + threadIdx.x;

    for (; i + stride < n4; i += 2 * stride) {
        float4 oa = o4[i];
        float4 ta = t4[i];
        float4 ob = o4[i + stride];
        float4 tb = t4[i + stride];
        float e[8];
        e[0] = rel_err(oa.x, ta.x); e[1] = rel_err(oa.y, ta.y);
        e[2] = rel_err(oa.z, ta.z); e[3] = rel_err(oa.w, ta.w);
        e[4] = rel_err(ob.x, tb.x); e[5] = rel_err(ob.y, tb.y);
        e[6] = rel_err(ob.z, tb.z); e[7] = rel_err(ob.w, tb.w);
#pragma unroll
        for (int j = 0; j < 8; j++) {
            unsigned int key = __float_as_uint(e[j]);
            unsigned int b = key >> 20;
            if (b < B1) {
                if ((j & 3) == 0) a0 += e[j];
                else if ((j & 3) == 1) a1 += e[j];
                else if ((j & 3) == 2) a2 += e[j];
                else a3 += e[j];
            } else if (b == B1) {
                unsigned int b2 = (key >> 8) & 0xFFFu;
                atomicAdd(&cnt2[b2], 1u);
                atomicAdd(&fs2[b2], e[j]);
            }
        }
    }
    for (; i < n4; i += stride) {
        float4 o = o4[i];
        float4 t = t4[i];
        float e[4];
        e[0] = rel_err(o.x, t.x); e[1] = rel_err(o.y, t.y);
        e[2] = rel_err(o.z, t.z); e[3] = rel_err(o.w, t.w);
#pragma unroll
        for (int j = 0; j < 4; j++) {
            unsigned int key = __float_as_uint(e[j]);
            unsigned int b = key >> 20;
            if (b < B1) {
                if (j == 0) a0 += e[j];
                else if (j == 1) a1 += e[j];
                else if (j == 2) a2 += e[j];
                else a3 += e[j];
            } else if (b == B1) {
                unsigned int b2 = (key >> 8) & 0xFFFu;
                atomicAdd(&cnt2[b2], 1u);
                atomicAdd(&fs2[b2], e[j]);
            }
        }
    }
    // tail
    int tail_base = n4 << 2;
    int gtid = blockIdx.x * blockDim.x + threadIdx.x;
    if (tail_base + gtid < n) {
        float e = rel_err(out[tail_base + gtid], tgt[tail_base + gtid]);
        unsigned int key = __float_as_uint(e);
        unsigned int b = key >> 20;
        if (b < B1) a0 += e;
        else if (b == B1) {
            unsigned int b2 = (key >> 8) & 0xFFFu;
            atomicAdd(&cnt2[b2], 1u);
            atomicAdd(&fs2[b2], e);
        }
    }

    // per-thread double, then block reduce -> one global double atomic per block
    double acc = ((double)a0 + (double)a1) + ((double)a2 + (double)a3);
    int lane = threadIdx.x & 31;
    int wid = threadIdx.x >> 5;
#pragma unroll
    for (int off = 16; off >= 1; off >>= 1)
        acc += __shfl_down_sync(FULLMASK, acc, off);
    if (lane == 0) wsum[wid] = acc;
    __syncthreads();
    if (threadIdx.x == 0) {
        double s = 0.0;
        int nw = blockDim.x >> 5;
        for (int w = 0; w < nw; w++) s += wsum[w];
        atomicAdd(&g_sum_below, s);
    }

    // flush level-2 histogram (counts + value partial sums)
    for (int b = threadIdx.x; b < NBINS; b += blockDim.x) {
        unsigned int c = cnt2[b];
        if (c) {
            atomicAdd(&g_hist2[b], c);
            atomicAdd(&g_sum2[b], (double)fs2[b]);
        }
    }
}

// ---------------- K4: finalize (parallel scan + parallel prefix sum) ----------------
__global__ __launch_bounds__(1024) void k_final(int n, float* __restrict__ result) {
    __shared__ unsigned int sB2;
    __shared__ unsigned long long sC2;
    __shared__ double wsum[32];

    long long k = keep_k(n);
    long long m = k - g_cbelow1;  // elements still needed from level-1 bin B1 (>= 1)

    select_bin_1024(g_hist2, m, &sB2, &sC2);
    __syncthreads();

    unsigned int B2 = sB2;
    long long cbelow2 = (long long)sC2;

    // parallel sum of g_sum2 for bins < B2
    double part = 0.0;
    for (int i = threadIdx.x; i < (int)B2; i += blockDim.x) part += g_sum2[i];
    int lane = threadIdx.x & 31;
    int wid = threadIdx.x >> 5;
#pragma unroll
    for (int off = 16; off >= 1; off >>= 1)
        part += __shfl_down_sync(FULLMASK, part, off);
    if (lane == 0) wsum[wid] = part;
    __syncthreads();
    if (threadIdx.x == 0) {
        double prefix2 = 0.0;
        for (int w = 0; w < 32; w++) prefix2 += wsum[w];
        long long r = m - cbelow2;  // elements taken from the boundary level-2 bin
        unsigned int key = (g_B1 << 20) | (B2 << 8) | 0x80u;  // midpoint of unresolved low byte
        double v = (double)__uint_as_float(key);
        double total = g_sum_below + prefix2 + (double)r * v;
        result[0] = (float)(total / (double)k);
    }
}

// ---------------- launch ----------------
extern "C" void kernel_launch(void* const* d_in, const int* in_sizes, int n_in,
                              void* d_out, int out_size) {
    const float* output = (const float*)d_in[0];
    const float* target = (const float*)d_in[1];
    int n = in_sizes[0];
    if (n <= 0) return;

    k_zero<<<16, 256>>>();
    k_hist1<<<592, 512>>>(output, target, n);
    k_select1<<<1, 1024>>>(n);
    k_pass2<<<592, 512>>>(output, target, n);
    k_final<<<1, 1024>>>(n, (float*)d_out);
}